// round 15
// baseline (speedup 1.0000x reference)
#include <cuda_runtime.h>

#define Bc 8
#define Pc 512
#define Dc 16
#define Ec 64
#define Hc 128

typedef unsigned long long u64;

// Scratch (no allocations allowed -> __device__ globals)
__device__ float g_a[Bc * Pc * Hc];     // a_s = ns @ We1[17:33]          (2 MB)
__device__ float g_c[Bc * Pc * Hc];     // c_r = nr @ We1[1:17] + be1     (2 MB)

// ---------------- packed f32x2 helpers (sm_103a) ----------------
__device__ __forceinline__ u64 add2(u64 a, u64 b) {
    u64 r; asm("add.rn.f32x2 %0,%1,%2;" : "=l"(r) : "l"(a), "l"(b)); return r;
}
__device__ __forceinline__ u64 fma2(u64 a, u64 b, u64 c) {
    u64 r; asm("fma.rn.f32x2 %0,%1,%2,%3;" : "=l"(r) : "l"(a), "l"(b), "l"(c)); return r;
}
__device__ __forceinline__ u64 pack2(float lo, float hi) {
    u64 r; asm("mov.b64 %0,{%1,%2};" : "=l"(r) : "f"(lo), "f"(hi)); return r;
}
__device__ __forceinline__ void unpack2(u64 x, float& lo, float& hi) {
    asm("mov.b64 {%0,%1},%2;" : "=f"(lo), "=f"(hi) : "l"(x));
}
// max(q, thresh) elementwise on a packed pair; pack/unpack are reg aliasing
__device__ __forceinline__ u64 max2t(u64 q, float tl, float th) {
    float lo, hi; unpack2(q, lo, hi);
    return pack2(fmaxf(lo, tl), fmaxf(hi, th));
}

// ---------------------------------------------------------------------------
// K1 (pre_ac): per-node a,c precompute only. 128 blocks x 256 threads,
// 32 nodes per block (thread = (k, node-half)).
// ---------------------------------------------------------------------------
__global__ void __launch_bounds__(256)
pre_ac_kernel(const float* __restrict__ h,
              const float* __restrict__ We1,
              const float* __restrict__ be1) {
    int t = threadIdx.x;
    int k = t & 127;
    int g = t >> 7;                  // 0/1 -> 16 nodes each
    int nb = blockIdx.x * 32;        // first node of this block

    __shared__ float nd[32][Dc];     // 2 KB
    ((float2*)nd)[t] = ((const float2*)(h + nb * Dc))[t];   // 512 floats
    __syncthreads();

    int n0 = g * 16;
    float a[16], c[16];
    float b1 = be1[k];
#pragma unroll
    for (int n = 0; n < 16; n++) { a[n] = 0.f; c[n] = b1; }

#pragma unroll
    for (int d = 0; d < Dc; d++) {
        float ws = We1[(17 + d) * Hc + k];
        float wr = We1[(1 + d) * Hc + k];
#pragma unroll
        for (int n = 0; n < 16; n++) {
            float x = nd[n0 + n][d];
            a[n] = fmaf(x, ws, a[n]);
            c[n] = fmaf(x, wr, c[n]);
        }
    }
#pragma unroll
    for (int n = 0; n < 16; n++) {
        g_a[(nb + n0 + n) * Hc + k] = a[n];
        g_c[(nb + n0 + n) * Hc + k] = c[n];
    }
}

// ---------------------------------------------------------------------------
// K2 (fused dist+edge+post): grid = 1024 (b, 4 receivers), 128 threads, 8 CTAs/SM.
// Thread = (sender-quarter q[0..3], k-quad kq[0..31]); 4 receivers in registers.
// Each LDS.128 dist load now feeds 4 k (wavefronts/pair-op cut 25%); av via
// LDG.128. Prologue computes dist in-block (receiver coords in registers).
// Main loop: hoisted-threshold identity
//   relu(d*w0 + a + c) = max(fma(d,w0,a), -c) + c   (bit-exact),
// batch-2 double-buffered av ring with literal-offset LDGs (final iter peeled).
// ---------------------------------------------------------------------------
__global__ void __launch_bounds__(128, 8)
edgepost_kernel(const float* __restrict__ h,
                const float* __restrict__ We1,
                const float* __restrict__ We2,
                const float* __restrict__ be2,
                const float* __restrict__ Wn1,
                const float* __restrict__ bn1,
                const float* __restrict__ Wn2,
                const float* __restrict__ bn2,
                float* __restrict__ out) {
    int b = blockIdx.x >> 7;
    int r0 = (blockIdx.x & 127) * 4;
    int node0 = b * Pc + r0;
    int t = threadIdx.x;
    int kq = t & 31;           // k-quad: k = 4*kq .. 4*kq+3
    int q  = t >> 5;           // sender quarter (128 each)
    int k0 = kq * 4;

    __shared__ __align__(16) u64 sbig[4 * Pc];    // 16 KB: dist tile -> partials/nin/hid
#define PBUF(qq, r, x) sbig[(((qq) * 4 + (r)) << 6) + (x)]
    __shared__ __align__(16) float Hs[4][Hc];     // 2 KB
    __shared__ float scoord[128][Dc + 1];         // 8.5 KB: staged sender coords
    float* nin = (float*)((char*)sbig + 8192);    // 4 x 80 floats, past 8 KB PBUF
    float* hid = (float*)((char*)sbig + 8192 + 1280);  // 4 x 128 floats

    u64 w0a = *(const u64*)(We1 + k0);      // dist weights k0..k0+1
    u64 w0b = *(const u64*)(We1 + k0 + 2);  // dist weights k0+2..k0+3

    float4 negc[4];            // -c for the 4 k of this thread, per receiver
    u64 acca[4], accb[4];
#pragma unroll
    for (int n = 0; n < 4; n++) {
        const float* cp = g_c + (node0 + n) * Hc + k0;
        negc[n].x = -cp[0]; negc[n].y = -cp[1];
        negc[n].z = -cp[2]; negc[n].w = -cp[3];
        acca[n] = 0ull; accb[n] = 0ull;
    }

    // ---- prologue: dist tile; receiver coords held in registers ----
    {
        int rv = t >> 5;          // receiver 0..3 (warp-uniform)
        int s0 = t & 31;
        const float4* rp = (const float4*)(h + (node0 + rv) * Dc);
        float4 rc0 = rp[0], rc1 = rp[1], rc2 = rp[2], rc3 = rp[3];

#pragma unroll
        for (int ch = 0; ch < 4; ch++) {
            __syncthreads();      // prev chunk consumed
            const float* hb = h + (b * Pc + ch * 128) * Dc;
#pragma unroll
            for (int i = 0; i < 16; i++) {
                int idx = t + i * 128;
                scoord[idx >> 4][idx & 15] = hb[idx];
            }
            __syncthreads();
#pragma unroll
            for (int i = 0; i < 4; i++) {
                int s = s0 + i * 32;
                const float* sc = &scoord[s][0];
                float accd = 0.f, df;
                df = rc0.x - sc[0];  accd = fmaf(df, df, accd);
                df = rc0.y - sc[1];  accd = fmaf(df, df, accd);
                df = rc0.z - sc[2];  accd = fmaf(df, df, accd);
                df = rc0.w - sc[3];  accd = fmaf(df, df, accd);
                df = rc1.x - sc[4];  accd = fmaf(df, df, accd);
                df = rc1.y - sc[5];  accd = fmaf(df, df, accd);
                df = rc1.z - sc[6];  accd = fmaf(df, df, accd);
                df = rc1.w - sc[7];  accd = fmaf(df, df, accd);
                df = rc2.x - sc[8];  accd = fmaf(df, df, accd);
                df = rc2.y - sc[9];  accd = fmaf(df, df, accd);
                df = rc2.z - sc[10]; accd = fmaf(df, df, accd);
                df = rc2.w - sc[11]; accd = fmaf(df, df, accd);
                df = rc3.x - sc[12]; accd = fmaf(df, df, accd);
                df = rc3.y - sc[13]; accd = fmaf(df, df, accd);
                df = rc3.z - sc[14]; accd = fmaf(df, df, accd);
                df = rc3.w - sc[15]; accd = fmaf(df, df, accd);
                float dist = sqrtf(accd);   // r==s -> accd==0 -> dist==0 exact
                sbig[rv * Pc + ch * 128 + s] = pack2(dist, dist);
            }
        }
    }
    __syncthreads();

    // ---- main loop: 128 senders / thread (this quarter), batch-2 ring ----
    const float* ap = g_a + (b * Pc + q * 128) * Hc + k0;   // moving base
    const u64* dp = sbig + q * 128;                          // moving base

    ulonglong2 A0, A1, B0, B1;   // av quads for 2 senders each buffer
    A0 = *(const ulonglong2*)(ap);
    A1 = *(const ulonglong2*)(ap + Hc);

#pragma unroll 2
    for (int ss = 0; ss < 124; ss += 4) {
        // prefetch buffer B (senders ss+2, ss+3) — literal offsets
        B0 = *(const ulonglong2*)(ap + 2 * Hc);
        B1 = *(const ulonglong2*)(ap + 3 * Hc);
        // compute senders ss, ss+1 with A
#pragma unroll
        for (int n = 0; n < 4; n++) {
            ulonglong2 d01 = *(const ulonglong2*)(dp + n * Pc);
            u64 m0a = max2t(fma2(d01.x, w0a, A0.x), negc[n].x, negc[n].y);
            u64 m0b = max2t(fma2(d01.x, w0b, A0.y), negc[n].z, negc[n].w);
            u64 m1a = max2t(fma2(d01.y, w0a, A1.x), negc[n].x, negc[n].y);
            u64 m1b = max2t(fma2(d01.y, w0b, A1.y), negc[n].z, negc[n].w);
            acca[n] = add2(acca[n], add2(m0a, m1a));
            accb[n] = add2(accb[n], add2(m0b, m1b));
        }
        // prefetch buffer A (senders ss+4, ss+5)
        A0 = *(const ulonglong2*)(ap + 4 * Hc);
        A1 = *(const ulonglong2*)(ap + 5 * Hc);
        // compute senders ss+2, ss+3 with B
#pragma unroll
        for (int n = 0; n < 4; n++) {
            ulonglong2 d01 = *(const ulonglong2*)(dp + n * Pc + 2);
            u64 m0a = max2t(fma2(d01.x, w0a, B0.x), negc[n].x, negc[n].y);
            u64 m0b = max2t(fma2(d01.x, w0b, B0.y), negc[n].z, negc[n].w);
            u64 m1a = max2t(fma2(d01.y, w0a, B1.x), negc[n].x, negc[n].y);
            u64 m1b = max2t(fma2(d01.y, w0b, B1.y), negc[n].z, negc[n].w);
            acca[n] = add2(acca[n], add2(m0a, m1a));
            accb[n] = add2(accb[n], add2(m0b, m1b));
        }
        ap += 4 * Hc;
        dp += 4;
    }
    // peeled final iteration (senders 124..127); A holds 124,125
    {
        B0 = *(const ulonglong2*)(ap + 2 * Hc);
        B1 = *(const ulonglong2*)(ap + 3 * Hc);
#pragma unroll
        for (int n = 0; n < 4; n++) {
            ulonglong2 d01 = *(const ulonglong2*)(dp + n * Pc);
            u64 m0a = max2t(fma2(d01.x, w0a, A0.x), negc[n].x, negc[n].y);
            u64 m0b = max2t(fma2(d01.x, w0b, A0.y), negc[n].z, negc[n].w);
            u64 m1a = max2t(fma2(d01.y, w0a, A1.x), negc[n].x, negc[n].y);
            u64 m1b = max2t(fma2(d01.y, w0b, A1.y), negc[n].z, negc[n].w);
            acca[n] = add2(acca[n], add2(m0a, m1a));
            accb[n] = add2(accb[n], add2(m0b, m1b));
        }
#pragma unroll
        for (int n = 0; n < 4; n++) {
            ulonglong2 d01 = *(const ulonglong2*)(dp + n * Pc + 2);
            u64 m0a = max2t(fma2(d01.x, w0a, B0.x), negc[n].x, negc[n].y);
            u64 m0b = max2t(fma2(d01.x, w0b, B0.y), negc[n].z, negc[n].w);
            u64 m1a = max2t(fma2(d01.y, w0a, B1.x), negc[n].x, negc[n].y);
            u64 m1b = max2t(fma2(d01.y, w0b, B1.y), negc[n].z, negc[n].w);
            acca[n] = add2(acca[n], add2(m0a, m1a));
            accb[n] = add2(accb[n], add2(m0b, m1b));
        }
    }

    // ---- cross-quarter reduce (reuse sbig) + epilogue correction ----
    __syncthreads();
#pragma unroll
    for (int n = 0; n < 4; n++) {
        PBUF(q, n, 2 * kq)     = acca[n];   // k-pair k0..k0+1
        PBUF(q, n, 2 * kq + 1) = accb[n];   // k-pair k0+2..k0+3
    }
    __syncthreads();

#pragma unroll
    for (int j = 0; j < 2; j++) {
        int idx = t + j * 128;        // 0..255
        int rcv = idx >> 6;           // 0..3
        int kx  = idx & 63;
        u64 s = add2(add2(PBUF(0, rcv, kx), PBUF(1, rcv, kx)),
                     add2(PBUF(2, rcv, kx), PBUF(3, rcv, kx)));
        int kk = kx * 2;
        float lo, hi; unpack2(s, lo, hi);
        // hsum = Sum_all max(q_s,-c) - max(a_r,-c) + 511*c
        // (self sender q = fma(0,w0,a_r) = a_r exactly; +c hoisted: 512-1 = 511)
        const float* apx = g_a + (node0 + rcv) * Hc + kk;
        const float* cpx = g_c + (node0 + rcv) * Hc + kk;
        Hs[rcv][kk]     = fmaf(511.0f, cpx[0], lo - fmaxf(apx[0], -cpx[0]));
        Hs[rcv][kk + 1] = fmaf(511.0f, cpx[1], hi - fmaxf(apx[1], -cpx[1]));
    }
    __syncthreads();   // PBUF fully consumed before nin (aliased) is written

    // node features into nin[:, 64:80]
    if (t < 64)
        nin[(t >> 4) * (Ec + Dc) + Ec + (t & 15)] = h[node0 * Dc + t];
    __syncthreads();

    // ---- Phase A: agg = hsum @ We2 + 511*be2.  thread = (j, node-pair) ----
    {
        int j = t & 63;
        int n0 = (t >> 6) * 2, n1 = n0 + 1;
        float b2 = 511.0f * be2[j];
        float a0 = b2, a1 = b2;
#pragma unroll 8
        for (int kk = 0; kk < Hc; kk += 4) {
            float w0s = We2[(kk + 0) * Ec + j];
            float w1s = We2[(kk + 1) * Ec + j];
            float w2s = We2[(kk + 2) * Ec + j];
            float w3s = We2[(kk + 3) * Ec + j];
            float4 v0 = *((const float4*)&Hs[n0][0] + (kk >> 2));
            float4 v1 = *((const float4*)&Hs[n1][0] + (kk >> 2));
            a0 = fmaf(v0.x, w0s, a0); a0 = fmaf(v0.y, w1s, a0);
            a0 = fmaf(v0.z, w2s, a0); a0 = fmaf(v0.w, w3s, a0);
            a1 = fmaf(v1.x, w0s, a1); a1 = fmaf(v1.y, w1s, a1);
            a1 = fmaf(v1.z, w2s, a1); a1 = fmaf(v1.w, w3s, a1);
        }
        nin[n0 * (Ec + Dc) + j] = a0;
        nin[n1 * (Ec + Dc) + j] = a1;
    }
    __syncthreads();

    // ---- Phase B: hidden layer. thread = hidden unit, 4 nodes blocked ----
    {
        int hu = t;
        float b1 = bn1[hu];
        float accs[4];
#pragma unroll
        for (int m = 0; m < 4; m++) accs[m] = b1;
#pragma unroll 5
        for (int i = 0; i < Ec + Dc; i += 4) {
            float w0s = Wn1[(i + 0) * Hc + hu];
            float w1s = Wn1[(i + 1) * Hc + hu];
            float w2s = Wn1[(i + 2) * Hc + hu];
            float w3s = Wn1[(i + 3) * Hc + hu];
#pragma unroll
            for (int m = 0; m < 4; m++) {
                float4 v = *((const float4*)(nin + m * (Ec + Dc)) + (i >> 2));
                accs[m] = fmaf(v.x, w0s, accs[m]);
                accs[m] = fmaf(v.y, w1s, accs[m]);
                accs[m] = fmaf(v.z, w2s, accs[m]);
                accs[m] = fmaf(v.w, w3s, accs[m]);
            }
        }
#pragma unroll
        for (int m = 0; m < 4; m++)
            hid[m * Hc + hu] = fmaxf(accs[m], 0.f);
    }
    __syncthreads();

    // ---- Phase C: output layer. 64 threads = (node, dim) ----
    if (t < 64) {
        int n = t >> 4, d = t & 15;
        float a0 = 0.f, a1 = 0.f, a2 = 0.f, a3 = 0.f;
#pragma unroll 8
        for (int kk = 0; kk < Hc; kk += 4) {
            float4 v = *((const float4*)(hid + n * Hc) + (kk >> 2));
            a0 = fmaf(v.x, Wn2[(kk + 0) * Dc + d], a0);
            a1 = fmaf(v.y, Wn2[(kk + 1) * Dc + d], a1);
            a2 = fmaf(v.z, Wn2[(kk + 2) * Dc + d], a2);
            a3 = fmaf(v.w, Wn2[(kk + 3) * Dc + d], a3);
        }
        out[node0 * Dc + t] = bn2[d] + ((a0 + a1) + (a2 + a3));
    }
#undef PBUF
}

// ---------------------------------------------------------------------------
extern "C" void kernel_launch(void* const* d_in, const int* in_sizes, int n_in,
                              void* d_out, int out_size) {
    const float* h   = (const float*)d_in[0];
    const float* We1 = (const float*)d_in[1];
    const float* be1 = (const float*)d_in[2];
    const float* We2 = (const float*)d_in[3];
    const float* be2 = (const float*)d_in[4];
    const float* Wn1 = (const float*)d_in[5];
    const float* bn1 = (const float*)d_in[6];
    const float* Wn2 = (const float*)d_in[7];
    const float* bn2 = (const float*)d_in[8];
    float* out = (float*)d_out;

    pre_ac_kernel<<<(Bc * Pc) / 32, 256>>>(h, We1, be1);
    edgepost_kernel<<<Bc * 128, 128>>>(h, We1, We2, be2, Wn1, bn1, Wn2, bn2, out);
}

// round 16
// speedup vs baseline: 1.1524x; 1.1524x over previous
#include <cuda_runtime.h>

#define Bc 8
#define Pc 512
#define Dc 16
#define Ec 64
#define Hc 128

typedef unsigned long long u64;

// Scratch (no allocations allowed -> __device__ globals)
__device__ float g_a[Bc * Pc * Hc];     // a_s = ns @ We1[17:33]          (2 MB)
__device__ float g_c[Bc * Pc * Hc];     // c_r = nr @ We1[1:17] + be1     (2 MB)

// ---------------- packed f32x2 helpers (sm_103a) ----------------
__device__ __forceinline__ u64 add2(u64 a, u64 b) {
    u64 r; asm("add.rn.f32x2 %0,%1,%2;" : "=l"(r) : "l"(a), "l"(b)); return r;
}
__device__ __forceinline__ u64 fma2(u64 a, u64 b, u64 c) {
    u64 r; asm("fma.rn.f32x2 %0,%1,%2,%3;" : "=l"(r) : "l"(a), "l"(b), "l"(c)); return r;
}
__device__ __forceinline__ u64 pack2(float lo, float hi) {
    u64 r; asm("mov.b64 %0,{%1,%2};" : "=l"(r) : "f"(lo), "f"(hi)); return r;
}
__device__ __forceinline__ void unpack2(u64 x, float& lo, float& hi) {
    asm("mov.b64 {%0,%1},%2;" : "=f"(lo), "=f"(hi) : "l"(x));
}
// max(q, thresh) elementwise on a packed pair; pack/unpack are reg aliasing
__device__ __forceinline__ u64 max2t(u64 q, float tl, float th) {
    float lo, hi; unpack2(q, lo, hi);
    return pack2(fmaxf(lo, tl), fmaxf(hi, th));
}

// ---------------------------------------------------------------------------
// K1 (pre_ac): per-node a,c precompute only. 128 blocks x 256 threads,
// 32 nodes per block (thread = (k, node-half)).
// ---------------------------------------------------------------------------
__global__ void __launch_bounds__(256)
pre_ac_kernel(const float* __restrict__ h,
              const float* __restrict__ We1,
              const float* __restrict__ be1) {
    int t = threadIdx.x;
    int k = t & 127;
    int g = t >> 7;                  // 0/1 -> 16 nodes each
    int nb = blockIdx.x * 32;        // first node of this block

    __shared__ float nd[32][Dc];     // 2 KB
    ((float2*)nd)[t] = ((const float2*)(h + nb * Dc))[t];   // 512 floats
    __syncthreads();

    int n0 = g * 16;
    float a[16], c[16];
    float b1 = be1[k];
#pragma unroll
    for (int n = 0; n < 16; n++) { a[n] = 0.f; c[n] = b1; }

#pragma unroll
    for (int d = 0; d < Dc; d++) {
        float ws = We1[(17 + d) * Hc + k];
        float wr = We1[(1 + d) * Hc + k];
#pragma unroll
        for (int n = 0; n < 16; n++) {
            float x = nd[n0 + n][d];
            a[n] = fmaf(x, ws, a[n]);
            c[n] = fmaf(x, wr, c[n]);
        }
    }
#pragma unroll
    for (int n = 0; n < 16; n++) {
        g_a[(nb + n0 + n) * Hc + k] = a[n];
        g_c[(nb + n0 + n) * Hc + k] = c[n];
    }
}

// ---------------------------------------------------------------------------
// K2 (fused dist+edge+post): grid = 1024 (b, 4 receivers), 128 threads, 8 CTAs/SM.
// Thread = (sender-half hf[0..1], k-pair kp[0..63]); 4 receivers in registers.
// Prologue: dist tile in-block; receiver coords in REGISTERS.
// Main loop (R14 shape, best known): hoisted-threshold identity
//   relu(d*w0 + a + c) = max(fma(d,w0,a), -c) + c   (bit-exact),
// batch-4 double-buffered av ring (MLP=8), literal-offset LDGs (final peeled),
// dist LDS front-batched per half-batch, unroll 4.
// ---------------------------------------------------------------------------
__global__ void __launch_bounds__(128, 8)
edgepost_kernel(const float* __restrict__ h,
                const float* __restrict__ We1,
                const float* __restrict__ We2,
                const float* __restrict__ be2,
                const float* __restrict__ Wn1,
                const float* __restrict__ bn1,
                const float* __restrict__ Wn2,
                const float* __restrict__ bn2,
                float* __restrict__ out) {
    int b = blockIdx.x >> 7;
    int r0 = (blockIdx.x & 127) * 4;
    int node0 = b * Pc + r0;
    int t = threadIdx.x;
    int kp = t & 63;           // k-pair: k = 2*kp, 2*kp+1
    int hf = t >> 6;           // sender half (256 each)
    int k0 = kp * 2;

    __shared__ __align__(16) u64 sbig[4 * Pc];    // 16 KB: dist tile -> partials/nin/hid
#define PBUF(hh, r, x) sbig[(((hh) * 4 + (r)) << 6) + (x)]
    __shared__ __align__(16) float Hs[4][Hc];     // 2 KB
    __shared__ float scoord[128][Dc + 1];         // 8.5 KB: staged sender coords
    float* nin = (float*)((char*)sbig + 4096);    // 4 x 80 floats (1.25 KB), past PBUF
    float* hid = (float*)((char*)sbig + 4096 + 1280);  // 4 x 128 floats (2 KB)

    u64 w0 = *(const u64*)(We1 + k0);  // row 0 = dist weight pair

    float ncl[4], nch[4];              // negated c halves (loop thresholds)
    u64 acc[4];
#pragma unroll
    for (int n = 0; n < 4; n++) {
        const float* cp = g_c + (node0 + n) * Hc + k0;
        ncl[n] = -cp[0];
        nch[n] = -cp[1];
        acc[n] = 0ull;
    }

    // ---- prologue: dist tile; receiver coords held in registers ----
    {
        int rv = t >> 5;          // receiver 0..3 (warp-uniform)
        int s0 = t & 31;
        const float4* rp = (const float4*)(h + (node0 + rv) * Dc);
        float4 rc0 = rp[0], rc1 = rp[1], rc2 = rp[2], rc3 = rp[3];

#pragma unroll
        for (int ch = 0; ch < 4; ch++) {
            __syncthreads();      // prev chunk consumed
            const float* hb = h + (b * Pc + ch * 128) * Dc;
#pragma unroll
            for (int i = 0; i < 16; i++) {
                int idx = t + i * 128;
                scoord[idx >> 4][idx & 15] = hb[idx];
            }
            __syncthreads();
#pragma unroll
            for (int i = 0; i < 4; i++) {
                int s = s0 + i * 32;
                const float* sc = &scoord[s][0];
                float accd = 0.f, df;
                df = rc0.x - sc[0];  accd = fmaf(df, df, accd);
                df = rc0.y - sc[1];  accd = fmaf(df, df, accd);
                df = rc0.z - sc[2];  accd = fmaf(df, df, accd);
                df = rc0.w - sc[3];  accd = fmaf(df, df, accd);
                df = rc1.x - sc[4];  accd = fmaf(df, df, accd);
                df = rc1.y - sc[5];  accd = fmaf(df, df, accd);
                df = rc1.z - sc[6];  accd = fmaf(df, df, accd);
                df = rc1.w - sc[7];  accd = fmaf(df, df, accd);
                df = rc2.x - sc[8];  accd = fmaf(df, df, accd);
                df = rc2.y - sc[9];  accd = fmaf(df, df, accd);
                df = rc2.z - sc[10]; accd = fmaf(df, df, accd);
                df = rc2.w - sc[11]; accd = fmaf(df, df, accd);
                df = rc3.x - sc[12]; accd = fmaf(df, df, accd);
                df = rc3.y - sc[13]; accd = fmaf(df, df, accd);
                df = rc3.z - sc[14]; accd = fmaf(df, df, accd);
                df = rc3.w - sc[15]; accd = fmaf(df, df, accd);
                float dist = sqrtf(accd);   // r==s -> accd==0 -> dist==0 exact
                sbig[rv * Pc + ch * 128 + s] = pack2(dist, dist);
            }
        }
    }
    __syncthreads();

    // ---- main loop: 256 senders / thread, batch-4 ring, literal offsets ----
    const float* ap = g_a + (b * Pc + hf * 256) * Hc + k0;   // moving base
    const u64* dp = sbig + hf * 256;                          // moving base

    u64 bA[4], bB[4];
#pragma unroll
    for (int i = 0; i < 4; i++)
        bA[i] = *(const u64*)(ap + i * Hc);

#pragma unroll 4
    for (int ss = 0; ss < 248; ss += 8) {
        // prefetch batch B (senders ss+4..ss+7) — literal offsets
#pragma unroll
        for (int i = 0; i < 4; i++)
            bB[i] = *(const u64*)(ap + (4 + i) * Hc);
        // front-batch the dist LDS for all 4 receivers (senders ss..ss+3)
        ulonglong2 dA01[4], dA23[4];
#pragma unroll
        for (int n = 0; n < 4; n++) {
            dA01[n] = *(const ulonglong2*)(dp + n * Pc);
            dA23[n] = *(const ulonglong2*)(dp + n * Pc + 2);
        }
#pragma unroll
        for (int n = 0; n < 4; n++) {
            u64 m0 = max2t(fma2(dA01[n].x, w0, bA[0]), ncl[n], nch[n]);
            u64 m1 = max2t(fma2(dA01[n].y, w0, bA[1]), ncl[n], nch[n]);
            u64 m2 = max2t(fma2(dA23[n].x, w0, bA[2]), ncl[n], nch[n]);
            u64 m3 = max2t(fma2(dA23[n].y, w0, bA[3]), ncl[n], nch[n]);
            acc[n] = add2(acc[n], add2(add2(m0, m1), add2(m2, m3)));
        }
        // prefetch batch A (senders ss+8..ss+11)
#pragma unroll
        for (int i = 0; i < 4; i++)
            bA[i] = *(const u64*)(ap + (8 + i) * Hc);
        // front-batch dist for senders ss+4..ss+7
        ulonglong2 dB01[4], dB23[4];
#pragma unroll
        for (int n = 0; n < 4; n++) {
            dB01[n] = *(const ulonglong2*)(dp + n * Pc + 4);
            dB23[n] = *(const ulonglong2*)(dp + n * Pc + 6);
        }
#pragma unroll
        for (int n = 0; n < 4; n++) {
            u64 m0 = max2t(fma2(dB01[n].x, w0, bB[0]), ncl[n], nch[n]);
            u64 m1 = max2t(fma2(dB01[n].y, w0, bB[1]), ncl[n], nch[n]);
            u64 m2 = max2t(fma2(dB23[n].x, w0, bB[2]), ncl[n], nch[n]);
            u64 m3 = max2t(fma2(dB23[n].y, w0, bB[3]), ncl[n], nch[n]);
            acc[n] = add2(acc[n], add2(add2(m0, m1), add2(m2, m3)));
        }
        ap += 8 * Hc;
        dp += 8;
    }
    // peeled final iteration (senders 248..255); bA holds 248..251
    {
#pragma unroll
        for (int i = 0; i < 4; i++)
            bB[i] = *(const u64*)(ap + (4 + i) * Hc);
#pragma unroll
        for (int n = 0; n < 4; n++) {
            ulonglong2 d01 = *(const ulonglong2*)(dp + n * Pc);
            ulonglong2 d23 = *(const ulonglong2*)(dp + n * Pc + 2);
            u64 m0 = max2t(fma2(d01.x, w0, bA[0]), ncl[n], nch[n]);
            u64 m1 = max2t(fma2(d01.y, w0, bA[1]), ncl[n], nch[n]);
            u64 m2 = max2t(fma2(d23.x, w0, bA[2]), ncl[n], nch[n]);
            u64 m3 = max2t(fma2(d23.y, w0, bA[3]), ncl[n], nch[n]);
            acc[n] = add2(acc[n], add2(add2(m0, m1), add2(m2, m3)));
        }
#pragma unroll
        for (int n = 0; n < 4; n++) {
            ulonglong2 d01 = *(const ulonglong2*)(dp + n * Pc + 4);
            ulonglong2 d23 = *(const ulonglong2*)(dp + n * Pc + 6);
            u64 m0 = max2t(fma2(d01.x, w0, bB[0]), ncl[n], nch[n]);
            u64 m1 = max2t(fma2(d01.y, w0, bB[1]), ncl[n], nch[n]);
            u64 m2 = max2t(fma2(d23.x, w0, bB[2]), ncl[n], nch[n]);
            u64 m3 = max2t(fma2(d23.y, w0, bB[3]), ncl[n], nch[n]);
            acc[n] = add2(acc[n], add2(add2(m0, m1), add2(m2, m3)));
        }
    }

    // ---- cross-half reduce (reuse sbig) + epilogue correction ----
    __syncthreads();
#pragma unroll
    for (int n = 0; n < 4; n++)
        PBUF(hf, n, kp) = acc[n];
    __syncthreads();

#pragma unroll
    for (int j = 0; j < 2; j++) {
        int idx = t + j * 128;        // 0..255
        int rcv = idx >> 6;           // 0..3
        int kx  = idx & 63;
        u64 s = add2(PBUF(0, rcv, kx), PBUF(1, rcv, kx));
        int kk = kx * 2;
        float lo, hi; unpack2(s, lo, hi);
        // hsum = Sum_all max(q_s,-c) - max(a_r,-c) + 511*c
        // (self sender q = fma(0,w0,a_r) = a_r exactly; +c hoisted: 512-1 = 511)
        const float* apx = g_a + (node0 + rcv) * Hc + kk;
        const float* cpx = g_c + (node0 + rcv) * Hc + kk;
        Hs[rcv][kk]     = fmaf(511.0f, cpx[0], lo - fmaxf(apx[0], -cpx[0]));
        Hs[rcv][kk + 1] = fmaf(511.0f, cpx[1], hi - fmaxf(apx[1], -cpx[1]));
    }
    __syncthreads();   // PBUF fully consumed before nin (aliased) is written

    // node features into nin[:, 64:80]
    if (t < 64)
        nin[(t >> 4) * (Ec + Dc) + Ec + (t & 15)] = h[node0 * Dc + t];
    __syncthreads();

    // ---- Phase A: agg = hsum @ We2 + 511*be2.  thread = (j, node-pair) ----
    {
        int j = t & 63;
        int n0 = (t >> 6) * 2, n1 = n0 + 1;
        float b2 = 511.0f * be2[j];
        float a0 = b2, a1 = b2;
#pragma unroll 8
        for (int kk = 0; kk < Hc; kk += 4) {
            float w0s = We2[(kk + 0) * Ec + j];
            float w1s = We2[(kk + 1) * Ec + j];
            float w2s = We2[(kk + 2) * Ec + j];
            float w3s = We2[(kk + 3) * Ec + j];
            float4 v0 = *((const float4*)&Hs[n0][0] + (kk >> 2));
            float4 v1 = *((const float4*)&Hs[n1][0] + (kk >> 2));
            a0 = fmaf(v0.x, w0s, a0); a0 = fmaf(v0.y, w1s, a0);
            a0 = fmaf(v0.z, w2s, a0); a0 = fmaf(v0.w, w3s, a0);
            a1 = fmaf(v1.x, w0s, a1); a1 = fmaf(v1.y, w1s, a1);
            a1 = fmaf(v1.z, w2s, a1); a1 = fmaf(v1.w, w3s, a1);
        }
        nin[n0 * (Ec + Dc) + j] = a0;
        nin[n1 * (Ec + Dc) + j] = a1;
    }
    __syncthreads();

    // ---- Phase B: hidden layer. thread = hidden unit, 4 nodes blocked ----
    {
        int hu = t;
        float b1 = bn1[hu];
        float accs[4];
#pragma unroll
        for (int m = 0; m < 4; m++) accs[m] = b1;
#pragma unroll 5
        for (int i = 0; i < Ec + Dc; i += 4) {
            float w0s = Wn1[(i + 0) * Hc + hu];
            float w1s = Wn1[(i + 1) * Hc + hu];
            float w2s = Wn1[(i + 2) * Hc + hu];
            float w3s = Wn1[(i + 3) * Hc + hu];
#pragma unroll
            for (int m = 0; m < 4; m++) {
                float4 v = *((const float4*)(nin + m * (Ec + Dc)) + (i >> 2));
                accs[m] = fmaf(v.x, w0s, accs[m]);
                accs[m] = fmaf(v.y, w1s, accs[m]);
                accs[m] = fmaf(v.z, w2s, accs[m]);
                accs[m] = fmaf(v.w, w3s, accs[m]);
            }
        }
#pragma unroll
        for (int m = 0; m < 4; m++)
            hid[m * Hc + hu] = fmaxf(accs[m], 0.f);
    }
    __syncthreads();

    // ---- Phase C: output layer. 64 threads = (node, dim) ----
    if (t < 64) {
        int n = t >> 4, d = t & 15;
        float a0 = 0.f, a1 = 0.f, a2 = 0.f, a3 = 0.f;
#pragma unroll 8
        for (int kk = 0; kk < Hc; kk += 4) {
            float4 v = *((const float4*)(hid + n * Hc) + (kk >> 2));
            a0 = fmaf(v.x, Wn2[(kk + 0) * Dc + d], a0);
            a1 = fmaf(v.y, Wn2[(kk + 1) * Dc + d], a1);
            a2 = fmaf(v.z, Wn2[(kk + 2) * Dc + d], a2);
            a3 = fmaf(v.w, Wn2[(kk + 3) * Dc + d], a3);
        }
        out[node0 * Dc + t] = bn2[d] + ((a0 + a1) + (a2 + a3));
    }
#undef PBUF
}

// ---------------------------------------------------------------------------
extern "C" void kernel_launch(void* const* d_in, const int* in_sizes, int n_in,
                              void* d_out, int out_size) {
    const float* h   = (const float*)d_in[0];
    const float* We1 = (const float*)d_in[1];
    const float* be1 = (const float*)d_in[2];
    const float* We2 = (const float*)d_in[3];
    const float* be2 = (const float*)d_in[4];
    const float* Wn1 = (const float*)d_in[5];
    const float* bn1 = (const float*)d_in[6];
    const float* Wn2 = (const float*)d_in[7];
    const float* bn2 = (const float*)d_in[8];
    float* out = (float*)d_out;

    pre_ac_kernel<<<(Bc * Pc) / 32, 256>>>(h, We1, be1);
    edgepost_kernel<<<Bc * 128, 128>>>(h, We1, We2, be2, Wn1, bn1, Wn2, bn2, out);
}